// round 7
// baseline (speedup 1.0000x reference)
#include <cuda_runtime.h>

#define FULL_MASK 0xffffffffu

typedef unsigned long long ull;

static constexpr int D_IN = 16;
static constexpr int DG   = 8;
static constexpr int DC   = 16;
static constexpr int HID  = 64;
static constexpr int NN   = 32;          // nodes per batch element (star graph)
static constexpr int MAXB = 65536;

static constexpr int E     = 64;         // elems per MLP block
static constexpr int PITCH = 66;         // float2 per activation row (pad: 16B-aligned, conflict-reduced)

// Scratch (allocation-free rule: __device__ globals)
__device__ float g_pooledT[(size_t)DG * MAXB];      // [feature][elem]
__device__ float g_W1p[32 * 12 * 4];                // packed W1: [j][ip][cpar][ipar]
__device__ float g_W2p[32 * 32 * 4];
__device__ float g_W3p[32 * 32 * 4];

// ---------------------------------------------------------------------------
// f32x2 packed helpers (Blackwell packed fp32 pipe)
// ---------------------------------------------------------------------------
__device__ __forceinline__ ull pack2(float lo, float hi) {
    ull r; asm("mov.b64 %0, {%1, %2};" : "=l"(r) : "f"(lo), "f"(hi)); return r;
}
__device__ __forceinline__ void unpack2(ull v, float& lo, float& hi) {
    asm("mov.b64 {%0, %1}, %2;" : "=f"(lo), "=f"(hi) : "l"(v));
}
__device__ __forceinline__ ull ffma2(ull a, ull b, ull c) {
    ull d; asm("fma.rn.f32x2 %0, %1, %2, %3;" : "=l"(d) : "l"(a), "l"(b), "l"(c));
    return d;
}
__device__ __forceinline__ ull splat2(float v) { return pack2(v, v); }

// Rational tanh (XLA-style): ~1e-7 rel err, single MUFU (RCP) instead of EX2+RCP.
__device__ __forceinline__ float ftanh(float x) {
    const float kMax = 7.90531110763549805f;
    float z = fminf(fmaxf(x, -kMax), kMax);
    float s = z * z;
    float p = fmaf(s, -2.76076847742355e-16f, 2.00018790482477e-13f);
    p = fmaf(p, s, -8.60467152213735e-11f);
    p = fmaf(p, s, 5.12229709037114e-08f);
    p = fmaf(p, s, 1.48572235717979e-05f);
    p = fmaf(p, s, 6.37261928875436e-04f);
    p = fmaf(p, s, 4.89352455891786e-03f);
    p = p * z;
    float q = fmaf(s, 1.18638912241465e-08f, 1.19825839466702e-06f);
    q = fmaf(q, s, 1.18534705686654e-04f);
    q = fmaf(q, s, 2.26843463243900e-03f);
    q = fmaf(q, s, 4.89352518554385e-03f);
    return __fdividef(p, q);
}

// ---------------------------------------------------------------------------
// Prep kernel: pack W1/W2/W3 so MLP lane j loads its column-pair weights as
// contiguous LDG.128s. packed[((j*NIP+ip)*2+cpar)*2+ipar] = W[2*ip+ipar][2*j+cpar]
// ---------------------------------------------------------------------------
__global__ void prep_kernel(const float* __restrict__ W1,
                            const float* __restrict__ W2,
                            const float* __restrict__ W3)
{
    int tid = threadIdx.x;
    for (int idx = tid; idx < 32 * 12 * 4; idx += blockDim.x) {
        int j = idx / 48, r = idx - j * 48;
        int ip = r >> 2, cpar = (r >> 1) & 1, ipar = r & 1;
        g_W1p[idx] = W1[(2 * ip + ipar) * 64 + 2 * j + cpar];
    }
    for (int idx = tid; idx < 32 * 32 * 4; idx += blockDim.x) {
        int j = idx >> 7, r = idx & 127;
        int ip = r >> 2, cpar = (r >> 1) & 1, ipar = r & 1;
        g_W2p[idx] = W2[(2 * ip + ipar) * 64 + 2 * j + cpar];
        g_W3p[idx] = W3[(2 * ip + ipar) * 64 + 2 * j + cpar];
    }
}

// ---------------------------------------------------------------------------
// Conv kernel: one warp handles TWO batch elements; lane = node index.
// (unchanged from R6 except rational tanh + transposed pooled store)
// ---------------------------------------------------------------------------
__device__ __forceinline__ void star_agg(const float* m, float* agg, int lane) {
    const bool b4 = (lane & 16) != 0;
    const bool b3 = (lane & 8) != 0;
    const bool b2 = (lane & 4) != 0;

    float mm[DG];
#pragma unroll
    for (int j = 0; j < DG; j++) mm[j] = (lane == 0) ? 0.0f : m[j];

    float fA[4];
#pragma unroll
    for (int k = 0; k < 4; k++) {
        float snd = b4 ? mm[k] : mm[4 + k];
        float kp  = b4 ? mm[4 + k] : mm[k];
        fA[k] = fmaxf(kp, __shfl_xor_sync(FULL_MASK, snd, 16));
    }
    float fB[2];
#pragma unroll
    for (int k = 0; k < 2; k++) {
        float snd = b3 ? fA[k] : fA[2 + k];
        float kp  = b3 ? fA[2 + k] : fA[k];
        fB[k] = fmaxf(kp, __shfl_xor_sync(FULL_MASK, snd, 8));
    }
    float bf = fmaxf(b2 ? fB[1] : fB[0],
                     __shfl_xor_sync(FULL_MASK, b2 ? fB[0] : fB[1], 4));
    bf = fmaxf(bf, __shfl_xor_sync(FULL_MASK, bf, 2));
    bf = fmaxf(bf, __shfl_xor_sync(FULL_MASK, bf, 1));

#pragma unroll
    for (int j = 0; j < DG; j++) {
        float val = (lane == 0) ? m[j] : bf;
        int   src = (lane == 0) ? (4 * j + 1) : 0;
        agg[j] = __shfl_sync(FULL_MASK, val, src);
    }
}

struct __align__(16) ConvSmem {
    float2 p1[D_IN * DG];
    float2 p2[DG * DG];
    float  wn1[DG * DG];
    float  wn2[DG * DG];
    float  bp1[DG], bc1[DG], bp2[DG], bc2[DG];
};

__global__ __launch_bounds__(128, 4) void conv_kernel(
    const float* __restrict__ x,
    const float* __restrict__ Wp1, const float* __restrict__ bp1,
    const float* __restrict__ Ws1, const float* __restrict__ Wn1, const float* __restrict__ bc1,
    const float* __restrict__ Wp2, const float* __restrict__ bp2,
    const float* __restrict__ Ws2, const float* __restrict__ Wn2, const float* __restrict__ bc2,
    int B)
{
    __shared__ ConvSmem s;
    int tid = threadIdx.x;
    if (tid < 128) s.p1[tid] = make_float2(Wp1[tid], Ws1[tid]);
    if (tid < 64) {
        s.p2[tid]  = make_float2(Wp2[tid], Ws2[tid]);
        s.wn1[tid] = Wn1[tid];
        s.wn2[tid] = Wn2[tid];
    }
    if (tid < 8) {
        s.bp1[tid] = bp1[tid]; s.bc1[tid] = bc1[tid];
        s.bp2[tid] = bp2[tid]; s.bc2[tid] = bc2[tid];
    }
    __syncthreads();

    int lane = tid & 31;
    int warp = tid >> 5;
    int b0   = blockIdx.x * 8 + warp * 2;
    if (b0 >= B) return;

    float xv[2][D_IN];
#pragma unroll
    for (int r = 0; r < 2; r++) {
        int bb = (b0 + r < B) ? (b0 + r) : b0;
        const float4* xp = (const float4*)(x + ((size_t)bb * NN + lane) * D_IN);
#pragma unroll
        for (int k = 0; k < 4; k++) {
            float4 v = xp[k];
            xv[r][4 * k + 0] = v.x; xv[r][4 * k + 1] = v.y;
            xv[r][4 * k + 2] = v.z; xv[r][4 * k + 3] = v.w;
        }
    }

    ull acc[2][DG];
#pragma unroll
    for (int r = 0; r < 2; r++)
#pragma unroll
        for (int j = 0; j < DG; j++) acc[r][j] = pack2(s.bp1[j], 0.0f);
#pragma unroll
    for (int i = 0; i < D_IN; i++) {
        const ulonglong2* wrow = (const ulonglong2*)(s.p1 + i * DG);
        ulonglong2 w0 = wrow[0], w1 = wrow[1], w2 = wrow[2], w3 = wrow[3];
#pragma unroll
        for (int r = 0; r < 2; r++) {
            ull vv = splat2(xv[r][i]);
            acc[r][0] = ffma2(vv, w0.x, acc[r][0]);
            acc[r][1] = ffma2(vv, w0.y, acc[r][1]);
            acc[r][2] = ffma2(vv, w1.x, acc[r][2]);
            acc[r][3] = ffma2(vv, w1.y, acc[r][3]);
            acc[r][4] = ffma2(vv, w2.x, acc[r][4]);
            acc[r][5] = ffma2(vv, w2.y, acc[r][5]);
            acc[r][6] = ffma2(vv, w3.x, acc[r][6]);
            acc[r][7] = ffma2(vv, w3.y, acc[r][7]);
        }
    }

    float m[2][DG], sv[2][DG];
#pragma unroll
    for (int r = 0; r < 2; r++)
#pragma unroll
        for (int j = 0; j < DG; j++) {
            float lo, hi; unpack2(acc[r][j], lo, hi);
            m[r][j] = fmaxf(lo, 0.0f); sv[r][j] = hi;
        }

    float agg[2][DG];
    star_agg(m[0], agg[0], lane);
    star_agg(m[1], agg[1], lane);

    ull hacc[2][4];
#pragma unroll
    for (int r = 0; r < 2; r++)
#pragma unroll
        for (int q = 0; q < 4; q++)
            hacc[r][q] = pack2(sv[r][2 * q] + s.bc1[2 * q], sv[r][2 * q + 1] + s.bc1[2 * q + 1]);
#pragma unroll
    for (int k = 0; k < DG; k++) {
        const ulonglong2* wn = (const ulonglong2*)(s.wn1) + k * 2;
        ulonglong2 wa = wn[0], wb = wn[1];
#pragma unroll
        for (int r = 0; r < 2; r++) {
            ull vv = splat2(agg[r][k]);
            hacc[r][0] = ffma2(vv, wa.x, hacc[r][0]);
            hacc[r][1] = ffma2(vv, wa.y, hacc[r][1]);
            hacc[r][2] = ffma2(vv, wb.x, hacc[r][2]);
            hacc[r][3] = ffma2(vv, wb.y, hacc[r][3]);
        }
    }
    float h[2][DG];
#pragma unroll
    for (int r = 0; r < 2; r++)
#pragma unroll
        for (int q = 0; q < 4; q++) {
            float lo, hi; unpack2(hacc[r][q], lo, hi);
            h[r][2 * q] = ftanh(lo); h[r][2 * q + 1] = ftanh(hi);
        }

    ull acc2[2][DG];
#pragma unroll
    for (int r = 0; r < 2; r++)
#pragma unroll
        for (int j = 0; j < DG; j++) acc2[r][j] = pack2(s.bp2[j], 0.0f);
#pragma unroll
    for (int k = 0; k < DG; k++) {
        const ulonglong2* wrow = (const ulonglong2*)(s.p2 + k * DG);
        ulonglong2 w0 = wrow[0], w1 = wrow[1], w2 = wrow[2], w3 = wrow[3];
#pragma unroll
        for (int r = 0; r < 2; r++) {
            ull vv = splat2(h[r][k]);
            acc2[r][0] = ffma2(vv, w0.x, acc2[r][0]);
            acc2[r][1] = ffma2(vv, w0.y, acc2[r][1]);
            acc2[r][2] = ffma2(vv, w1.x, acc2[r][2]);
            acc2[r][3] = ffma2(vv, w1.y, acc2[r][3]);
            acc2[r][4] = ffma2(vv, w2.x, acc2[r][4]);
            acc2[r][5] = ffma2(vv, w2.y, acc2[r][5]);
            acc2[r][6] = ffma2(vv, w3.x, acc2[r][6]);
            acc2[r][7] = ffma2(vv, w3.y, acc2[r][7]);
        }
    }
    float m2[2][DG], s2[2][DG];
#pragma unroll
    for (int r = 0; r < 2; r++)
#pragma unroll
        for (int j = 0; j < DG; j++) {
            float lo, hi; unpack2(acc2[r][j], lo, hi);
            m2[r][j] = fmaxf(lo, 0.0f); s2[r][j] = hi;
        }

    float agg2[2][DG];
    star_agg(m2[0], agg2[0], lane);
    star_agg(m2[1], agg2[1], lane);

    ull gacc[2][4];
#pragma unroll
    for (int r = 0; r < 2; r++)
#pragma unroll
        for (int q = 0; q < 4; q++)
            gacc[r][q] = pack2(s2[r][2 * q] + s.bc2[2 * q], s2[r][2 * q + 1] + s.bc2[2 * q + 1]);
#pragma unroll
    for (int k = 0; k < DG; k++) {
        const ulonglong2* wn = (const ulonglong2*)(s.wn2) + k * 2;
        ulonglong2 wa = wn[0], wb = wn[1];
#pragma unroll
        for (int r = 0; r < 2; r++) {
            ull vv = splat2(agg2[r][k]);
            gacc[r][0] = ffma2(vv, wa.x, gacc[r][0]);
            gacc[r][1] = ffma2(vv, wa.y, gacc[r][1]);
            gacc[r][2] = ffma2(vv, wb.x, gacc[r][2]);
            gacc[r][3] = ffma2(vv, wb.y, gacc[r][3]);
        }
    }

    const bool b4 = (lane & 16) != 0;
    const bool b3 = (lane & 8) != 0;
    const bool b2 = (lane & 4) != 0;
#pragma unroll
    for (int r = 0; r < 2; r++) {
        float g[DG];
#pragma unroll
        for (int q = 0; q < 4; q++) unpack2(gacc[r][q], g[2 * q], g[2 * q + 1]);
        float fA[4];
#pragma unroll
        for (int k = 0; k < 4; k++) {
            float snd = b4 ? g[k] : g[4 + k];
            float kp  = b4 ? g[4 + k] : g[k];
            fA[k] = kp + __shfl_xor_sync(FULL_MASK, snd, 16);
        }
        float fB[2];
#pragma unroll
        for (int k = 0; k < 2; k++) {
            float snd = b3 ? fA[k] : fA[2 + k];
            float kp  = b3 ? fA[2 + k] : fA[k];
            fB[k] = kp + __shfl_xor_sync(FULL_MASK, snd, 8);
        }
        float v = (b2 ? fB[1] : fB[0]) +
                  __shfl_xor_sync(FULL_MASK, b2 ? fB[0] : fB[1], 4);
        v += __shfl_xor_sync(FULL_MASK, v, 2);
        v += __shfl_xor_sync(FULL_MASK, v, 1);
        // lane 4j holds sum of feature j -> transposed store
        if (((lane & 3) == 0) && (b0 + r < B))
            g_pooledT[(size_t)(lane >> 2) * B + (b0 + r)] = v * (1.0f / (float)NN);
    }
}

// ---------------------------------------------------------------------------
// MLP kernel v4: warp-cooperative, weights in registers.
// Block = 128 threads (4 warps), E=64 elems/block; warp owns 16 elems,
// processed in 4 groups of 4. Lane j owns output columns (2j, 2j+1).
// Activations in smem as [feature-pair][elem] float2 rows (PITCH=66).
// ---------------------------------------------------------------------------
__global__ __launch_bounds__(128, 2) void mlp_kernel(
    const float* __restrict__ other,
    const float* __restrict__ b1, const float* __restrict__ b2,
    const float* __restrict__ b3,
    const float* __restrict__ W4, const float* __restrict__ b4,
    float* __restrict__ out, int B)
{
    __shared__ __align__(16) float2 act0[12 * PITCH];
    __shared__ __align__(16) float2 act1[32 * PITCH];
    __shared__ __align__(16) float2 act2[32 * PITCH];

    int tid  = threadIdx.x;
    int lane = tid & 31;
    int warp = tid >> 5;
    int eb   = blockIdx.x * E;

    // ---- stage A: build act0 = inputs [24 features][E elems], pair-major ----
    for (int idx = tid; idx < DG * E; idx += 128) {
        int j = idx >> 6;           // feature 0..7
        int t = idx & 63;
        int e = eb + t; if (e >= B) e = B - 1;
        float v = g_pooledT[(size_t)j * B + e];
        ((float*)&act0[(j >> 1) * PITCH + t])[j & 1] = v;
    }
    if (tid < E) {
        int e = eb + tid; if (e >= B) e = B - 1;
        const float4* op = (const float4*)(other + (size_t)e * DC);
#pragma unroll
        for (int k = 0; k < 4; k++) {
            float4 v = op[k];
            act0[(4 + 2 * k) * PITCH + tid] = make_float2(v.x, v.y);
            act0[(5 + 2 * k) * PITCH + tid] = make_float2(v.z, v.w);
        }
    }
    __syncthreads();

    const int e0w = warp * 16;      // warp's first local column
    ull w[32][2];                   // per-lane weight regs (column pair, input-pair packed)

    // ---- layer 1: 24 -> 64 ----
    {
        const ulonglong2* wp = (const ulonglong2*)(g_W1p) + lane * 12;
#pragma unroll
        for (int ip = 0; ip < 12; ip++) { ulonglong2 t2 = wp[ip]; w[ip][0] = t2.x; w[ip][1] = t2.y; }
        float2 bv = *(const float2*)(b1 + 2 * lane);
        for (int grp = 0; grp < 4; grp++) {
            int ecol = e0w + grp * 4;
            ull a00 = 0, a01 = 0, a02 = 0, a03 = 0, a10 = 0, a11 = 0, a12 = 0, a13 = 0;
#pragma unroll
            for (int ip = 0; ip < 12; ip++) {
                const ulonglong2* src = (const ulonglong2*)(act0 + ip * PITCH + ecol);
                ulonglong2 iA = src[0], iB = src[1];
                a00 = ffma2(iA.x, w[ip][0], a00); a10 = ffma2(iA.x, w[ip][1], a10);
                a01 = ffma2(iA.y, w[ip][0], a01); a11 = ffma2(iA.y, w[ip][1], a11);
                a02 = ffma2(iB.x, w[ip][0], a02); a12 = ffma2(iB.x, w[ip][1], a12);
                a03 = ffma2(iB.y, w[ip][0], a03); a13 = ffma2(iB.y, w[ip][1], a13);
            }
            ull a0[4] = {a00, a01, a02, a03}, a1[4] = {a10, a11, a12, a13};
#pragma unroll
            for (int e = 0; e < 4; e++) {
                float l0, h0, l1, h1;
                unpack2(a0[e], l0, h0); unpack2(a1[e], l1, h1);
                act1[lane * PITCH + ecol + e] =
                    make_float2(fmaxf(l0 + h0 + bv.x, 0.0f), fmaxf(l1 + h1 + bv.y, 0.0f));
            }
        }
    }
    __syncwarp();

    // ---- layer 2: 64 -> 64 ----
    {
        const ulonglong2* wp = (const ulonglong2*)(g_W2p) + lane * 32;
#pragma unroll
        for (int ip = 0; ip < 32; ip++) { ulonglong2 t2 = wp[ip]; w[ip][0] = t2.x; w[ip][1] = t2.y; }
        float2 bv = *(const float2*)(b2 + 2 * lane);
        for (int grp = 0; grp < 4; grp++) {
            int ecol = e0w + grp * 4;
            ull a00 = 0, a01 = 0, a02 = 0, a03 = 0, a10 = 0, a11 = 0, a12 = 0, a13 = 0;
#pragma unroll
            for (int ip = 0; ip < 32; ip++) {
                const ulonglong2* src = (const ulonglong2*)(act1 + ip * PITCH + ecol);
                ulonglong2 iA = src[0], iB = src[1];
                a00 = ffma2(iA.x, w[ip][0], a00); a10 = ffma2(iA.x, w[ip][1], a10);
                a01 = ffma2(iA.y, w[ip][0], a01); a11 = ffma2(iA.y, w[ip][1], a11);
                a02 = ffma2(iB.x, w[ip][0], a02); a12 = ffma2(iB.x, w[ip][1], a12);
                a03 = ffma2(iB.y, w[ip][0], a03); a13 = ffma2(iB.y, w[ip][1], a13);
            }
            ull a0[4] = {a00, a01, a02, a03}, a1[4] = {a10, a11, a12, a13};
#pragma unroll
            for (int e = 0; e < 4; e++) {
                float l0, h0, l1, h1;
                unpack2(a0[e], l0, h0); unpack2(a1[e], l1, h1);
                act2[lane * PITCH + ecol + e] =
                    make_float2(fmaxf(l0 + h0 + bv.x, 0.0f), fmaxf(l1 + h1 + bv.y, 0.0f));
            }
        }
    }
    __syncwarp();

    // ---- layer 3 (64->64) fused with output layer (64->4) ----
    {
        const ulonglong2* wp = (const ulonglong2*)(g_W3p) + lane * 32;
#pragma unroll
        for (int ip = 0; ip < 32; ip++) { ulonglong2 t2 = wp[ip]; w[ip][0] = t2.x; w[ip][1] = t2.y; }
        float2 bv = *(const float2*)(b3 + 2 * lane);
        // W4 rows 2*lane, 2*lane+1 (each row = 4 floats = 16B)
        ulonglong2 w4a = *(const ulonglong2*)(W4 + (2 * lane) * 4);
        ulonglong2 w4b = *(const ulonglong2*)(W4 + (2 * lane + 1) * 4);
        float4 bo = *(const float4*)(b4);

        const bool bb4 = (lane & 16) != 0;
        const bool bb3 = (lane & 8) != 0;
        const bool bb2 = (lane & 4) != 0;
        const bool bb1 = (lane & 2) != 0;

        for (int grp = 0; grp < 4; grp++) {
            int ecol = e0w + grp * 4;
            ull a00 = 0, a01 = 0, a02 = 0, a03 = 0, a10 = 0, a11 = 0, a12 = 0, a13 = 0;
#pragma unroll
            for (int ip = 0; ip < 32; ip++) {
                const ulonglong2* src = (const ulonglong2*)(act2 + ip * PITCH + ecol);
                ulonglong2 iA = src[0], iB = src[1];
                a00 = ffma2(iA.x, w[ip][0], a00); a10 = ffma2(iA.x, w[ip][1], a10);
                a01 = ffma2(iA.y, w[ip][0], a01); a11 = ffma2(iA.y, w[ip][1], a11);
                a02 = ffma2(iB.x, w[ip][0], a02); a12 = ffma2(iB.x, w[ip][1], a12);
                a03 = ffma2(iB.y, w[ip][0], a03); a13 = ffma2(iB.y, w[ip][1], a13);
            }
            ull a0[4] = {a00, a01, a02, a03}, a1[4] = {a10, a11, a12, a13};

            // h3 for this lane's two feature columns, 4 elems
            float h0[4], h1[4];
#pragma unroll
            for (int e = 0; e < 4; e++) {
                float l0, hh0, l1, hh1;
                unpack2(a0[e], l0, hh0); unpack2(a1[e], l1, hh1);
                h0[e] = fmaxf(l0 + hh0 + bv.x, 0.0f);
                h1[e] = fmaxf(l1 + hh1 + bv.y, 0.0f);
            }

            // output partials: p[q][e], q=0 -> (o0,o1), q=1 -> (o2,o3)
            ull p0[4], p1[4];
#pragma unroll
            for (int e = 0; e < 4; e++) {
                ull s0 = splat2(h0[e]);
                ull s1 = splat2(h1[e]);
                p0[e] = ffma2(s0, w4a.x, ffma2(s1, w4b.x, 0ULL));
                p1[e] = ffma2(s0, w4a.y, ffma2(s1, w4b.y, 0ULL));
            }

            // cur[k], k = e*4 + o
            float cur[16];
#pragma unroll
            for (int e = 0; e < 4; e++) {
                unpack2(p0[e], cur[e * 4 + 0], cur[e * 4 + 1]);
                unpack2(p1[e], cur[e * 4 + 2], cur[e * 4 + 3]);
            }
            // feature-split butterfly sum over 32 lanes (16 shfl)
            float n8[8];
#pragma unroll
            for (int t = 0; t < 8; t++) {
                float snd = bb4 ? cur[t] : cur[8 + t];
                float kp  = bb4 ? cur[8 + t] : cur[t];
                n8[t] = kp + __shfl_xor_sync(FULL_MASK, snd, 16);
            }
            float n4[4];
#pragma unroll
            for (int t = 0; t < 4; t++) {
                float snd = bb3 ? n8[t] : n8[4 + t];
                float kp  = bb3 ? n8[4 + t] : n8[t];
                n4[t] = kp + __shfl_xor_sync(FULL_MASK, snd, 8);
            }
            float n2[2];
#pragma unroll
            for (int t = 0; t < 2; t++) {
                float snd = bb2 ? n4[t] : n4[2 + t];
                float kp  = bb2 ? n4[2 + t] : n4[t];
                n2[t] = kp + __shfl_xor_sync(FULL_MASK, snd, 4);
            }
            float n1 = (bb1 ? n2[1] : n2[0]) +
                       __shfl_xor_sync(FULL_MASK, bb1 ? n2[0] : n2[1], 2);
            n1 += __shfl_xor_sync(FULL_MASK, n1, 1);
            // lane L holds k = (L>>1)&15; even lanes write
            if (!(lane & 1)) {
                int k = (lane >> 1) & 15;
                int e = k >> 2, o = k & 3;
                int eg = eb + ecol + e;
                if (eg < B) {
                    float bias = (o & 2) ? ((o & 1) ? bo.w : bo.z)
                                         : ((o & 1) ? bo.y : bo.x);
                    out[(size_t)eg * 4 + o] = ftanh(n1 + bias);
                }
            }
        }
    }
}

// ---------------------------------------------------------------------------

extern "C" void kernel_launch(void* const* d_in, const int* in_sizes, int n_in,
                              void* d_out, int out_size)
{
    const float* x     = (const float*)d_in[0];
    const float* other = (const float*)d_in[1];
    // d_in[2..4] = src/dst/node_seg: star graph is fixed, structure hardcoded.
    const float* Wp1 = (const float*)d_in[5];
    const float* bp1 = (const float*)d_in[6];
    const float* Ws1 = (const float*)d_in[7];
    const float* Wn1 = (const float*)d_in[8];
    const float* bc1 = (const float*)d_in[9];
    const float* Wp2 = (const float*)d_in[10];
    const float* bp2 = (const float*)d_in[11];
    const float* Ws2 = (const float*)d_in[12];
    const float* Wn2 = (const float*)d_in[13];
    const float* bc2 = (const float*)d_in[14];
    const float* W1  = (const float*)d_in[15];
    const float* bf1 = (const float*)d_in[16];
    const float* W2  = (const float*)d_in[17];
    const float* bf2 = (const float*)d_in[18];
    const float* W3  = (const float*)d_in[19];
    const float* bf3 = (const float*)d_in[20];
    const float* W4  = (const float*)d_in[21];
    const float* bf4 = (const float*)d_in[22];

    int B = in_sizes[1] / DC;   // other_obs is [B, 16]

    prep_kernel<<<1, 256>>>(W1, W2, W3);
    conv_kernel<<<(B + 7) / 8, 128>>>(x, Wp1, bp1, Ws1, Wn1, bc1,
                                      Wp2, bp2, Ws2, Wn2, bc2, B);
    mlp_kernel<<<(B + E - 1) / E, 128>>>(other, bf1, bf2, bf3,
                                         W4, bf4, (float*)d_out, B);
}

// round 8
// speedup vs baseline: 1.1581x; 1.1581x over previous
#include <cuda_runtime.h>

#define FULL_MASK 0xffffffffu

typedef unsigned long long ull;

static constexpr int D_IN = 16;
static constexpr int DG   = 8;
static constexpr int DC   = 16;
static constexpr int HID  = 64;
static constexpr int NN   = 32;          // nodes per batch element (star graph)
static constexpr int MAXB = 65536;
static constexpr int R    = 4;           // elems per conv warp

// Scratch for pooled conv output (allocation-free rule: __device__ global)
__device__ float g_pooled[(size_t)MAXB * DG];

// ---------------------------------------------------------------------------
// f32x2 packed helpers (Blackwell packed fp32 pipe)
// ---------------------------------------------------------------------------
__device__ __forceinline__ ull pack2(float lo, float hi) {
    ull r; asm("mov.b64 %0, {%1, %2};" : "=l"(r) : "f"(lo), "f"(hi)); return r;
}
__device__ __forceinline__ void unpack2(ull v, float& lo, float& hi) {
    asm("mov.b64 {%0, %1}, %2;" : "=f"(lo), "=f"(hi) : "l"(v));
}
__device__ __forceinline__ ull ffma2(ull a, ull b, ull c) {
    ull d; asm("fma.rn.f32x2 %0, %1, %2, %3;" : "=l"(d) : "l"(a), "l"(b), "l"(c));
    return d;
}
__device__ __forceinline__ ull mul2(ull a, ull b) {
    ull d; asm("mul.rn.f32x2 %0, %1, %2;" : "=l"(d) : "l"(a), "l"(b));
    return d;
}
__device__ __forceinline__ ull splat2(float v) { return pack2(v, v); }

// Packed rational tanh (XLA-style poly): ~1e-7 rel err, 2 values at once.
__device__ __forceinline__ ull ftanh2(ull x2) {
    const float kMax = 7.90531110763549805f;
    float a, b; unpack2(x2, a, b);
    a = fminf(fmaxf(a, -kMax), kMax);
    b = fminf(fmaxf(b, -kMax), kMax);
    ull z = pack2(a, b);
    ull s = mul2(z, z);
    ull p = ffma2(s, splat2(-2.76076847742355e-16f), splat2(2.00018790482477e-13f));
    p = ffma2(p, s, splat2(-8.60467152213735e-11f));
    p = ffma2(p, s, splat2(5.12229709037114e-08f));
    p = ffma2(p, s, splat2(1.48572235717979e-05f));
    p = ffma2(p, s, splat2(6.37261928875436e-04f));
    p = ffma2(p, s, splat2(4.89352455891786e-03f));
    p = mul2(p, z);
    ull q = ffma2(s, splat2(1.18638912241465e-08f), splat2(1.19825839466702e-06f));
    q = ffma2(q, s, splat2(1.18534705686654e-04f));
    q = ffma2(q, s, splat2(2.26843463243900e-03f));
    q = ffma2(q, s, splat2(4.89352518554385e-03f));
    float pl, ph, ql, qh; unpack2(p, pl, ph); unpack2(q, ql, qh);
    return pack2(__fdividef(pl, ql), __fdividef(ph, qh));
}

// ---------------------------------------------------------------------------
// Conv kernel: one warp handles FOUR batch elements; lane = node index
// (node 0 = hub of the star).
// ---------------------------------------------------------------------------

// Star aggregation, 17 shfl total.
__device__ __forceinline__ void star_agg(const float* m, float* agg, int lane) {
    const bool b4 = (lane & 16) != 0;
    const bool b3 = (lane & 8) != 0;
    const bool b2 = (lane & 4) != 0;

    float mm[DG];
#pragma unroll
    for (int j = 0; j < DG; j++) mm[j] = (lane == 0) ? 0.0f : m[j];

    float fA[4];
#pragma unroll
    for (int k = 0; k < 4; k++) {
        float snd = b4 ? mm[k] : mm[4 + k];
        float kp  = b4 ? mm[4 + k] : mm[k];
        fA[k] = fmaxf(kp, __shfl_xor_sync(FULL_MASK, snd, 16));
    }
    float fB[2];
#pragma unroll
    for (int k = 0; k < 2; k++) {
        float snd = b3 ? fA[k] : fA[2 + k];
        float kp  = b3 ? fA[2 + k] : fA[k];
        fB[k] = fmaxf(kp, __shfl_xor_sync(FULL_MASK, snd, 8));
    }
    float bf = fmaxf(b2 ? fB[1] : fB[0],
                     __shfl_xor_sync(FULL_MASK, b2 ? fB[0] : fB[1], 4));
    bf = fmaxf(bf, __shfl_xor_sync(FULL_MASK, bf, 2));
    bf = fmaxf(bf, __shfl_xor_sync(FULL_MASK, bf, 1));
    // every lane in group j (lanes 4j..4j+3) now holds leaf-max of feature j

#pragma unroll
    for (int j = 0; j < DG; j++) {
        float val = (lane == 0) ? m[j] : bf;
        int   src = (lane == 0) ? (4 * j + 1) : 0;
        agg[j] = __shfl_sync(FULL_MASK, val, src);
    }
}

struct __align__(16) ConvSmem {
    float2 p1[D_IN * DG];   // (Wp1, Ws1) interleaved
    float2 p2[DG * DG];     // (Wp2, Ws2) interleaved
    float  wn1[DG * DG];
    float  wn2[DG * DG];
    float  bp1[DG], bc1[DG], bp2[DG], bc2[DG];
};

__global__ __launch_bounds__(128, 3) void conv_kernel(
    const float* __restrict__ x,
    const float* __restrict__ Wp1, const float* __restrict__ bp1,
    const float* __restrict__ Ws1, const float* __restrict__ Wn1, const float* __restrict__ bc1,
    const float* __restrict__ Wp2, const float* __restrict__ bp2,
    const float* __restrict__ Ws2, const float* __restrict__ Wn2, const float* __restrict__ bc2,
    int B)
{
    __shared__ ConvSmem s;
    int tid = threadIdx.x;
    if (tid < 128) s.p1[tid] = make_float2(Wp1[tid], Ws1[tid]);
    if (tid < 64) {
        s.p2[tid]  = make_float2(Wp2[tid], Ws2[tid]);
        s.wn1[tid] = Wn1[tid];
        s.wn2[tid] = Wn2[tid];
    }
    if (tid < 8) {
        s.bp1[tid] = bp1[tid]; s.bc1[tid] = bc1[tid];
        s.bp2[tid] = bp2[tid]; s.bc2[tid] = bc2[tid];
    }
    __syncthreads();

    int lane = tid & 31;
    int warp = tid >> 5;
    int b0   = blockIdx.x * (4 * R) + warp * R;   // this warp: elems b0..b0+3
    if (b0 >= B) return;

    // Load node features for all R elements (64B contiguous per lane each).
    float xv[R][D_IN];
#pragma unroll
    for (int r = 0; r < R; r++) {
        int bb = (b0 + r < B) ? (b0 + r) : b0;   // clamp (garbage ok, store guarded)
        const float4* xp = (const float4*)(x + ((size_t)bb * NN + lane) * D_IN);
#pragma unroll
        for (int k = 0; k < 4; k++) {
            float4 v = xp[k];
            xv[r][4 * k + 0] = v.x; xv[r][4 * k + 1] = v.y;
            xv[r][4 * k + 2] = v.z; xv[r][4 * k + 3] = v.w;
        }
    }

    // ---- conv1: packed (m | sv) dual matvec, weights shared across r ----
    ull acc[R][DG];
#pragma unroll
    for (int r = 0; r < R; r++)
#pragma unroll
        for (int j = 0; j < DG; j++) acc[r][j] = pack2(s.bp1[j], 0.0f);
#pragma unroll
    for (int i = 0; i < D_IN; i++) {
        const ulonglong2* wrow = (const ulonglong2*)(s.p1 + i * DG);
        ulonglong2 w0 = wrow[0], w1 = wrow[1], w2 = wrow[2], w3 = wrow[3];
#pragma unroll
        for (int r = 0; r < R; r++) {
            ull vv = splat2(xv[r][i]);
            acc[r][0] = ffma2(vv, w0.x, acc[r][0]);
            acc[r][1] = ffma2(vv, w0.y, acc[r][1]);
            acc[r][2] = ffma2(vv, w1.x, acc[r][2]);
            acc[r][3] = ffma2(vv, w1.y, acc[r][3]);
            acc[r][4] = ffma2(vv, w2.x, acc[r][4]);
            acc[r][5] = ffma2(vv, w2.y, acc[r][5]);
            acc[r][6] = ffma2(vv, w3.x, acc[r][6]);
            acc[r][7] = ffma2(vv, w3.y, acc[r][7]);
        }
    }

    float m[R][DG], sv[R][DG];
#pragma unroll
    for (int r = 0; r < R; r++)
#pragma unroll
        for (int j = 0; j < DG; j++) {
            float lo, hi; unpack2(acc[r][j], lo, hi);
            m[r][j] = fmaxf(lo, 0.0f); sv[r][j] = hi;
        }

    float agg[R][DG];
#pragma unroll
    for (int r = 0; r < R; r++) star_agg(m[r], agg[r], lane);

    // h = tanh(sv + bc1 + agg @ Wn1)
    float h[R][DG];
#pragma unroll
    for (int r = 0; r < R; r++) {
        ull hacc[4];
#pragma unroll
        for (int q = 0; q < 4; q++)
            hacc[q] = pack2(sv[r][2 * q] + s.bc1[2 * q], sv[r][2 * q + 1] + s.bc1[2 * q + 1]);
#pragma unroll
        for (int k = 0; k < DG; k++) {
            const ulonglong2* wn = (const ulonglong2*)(s.wn1) + k * 2;
            ulonglong2 wa = wn[0], wb = wn[1];
            ull vv = splat2(agg[r][k]);
            hacc[0] = ffma2(vv, wa.x, hacc[0]);
            hacc[1] = ffma2(vv, wa.y, hacc[1]);
            hacc[2] = ffma2(vv, wb.x, hacc[2]);
            hacc[3] = ffma2(vv, wb.y, hacc[3]);
        }
#pragma unroll
        for (int q = 0; q < 4; q++) {
            ull t = ftanh2(hacc[q]);
            unpack2(t, h[r][2 * q], h[r][2 * q + 1]);
        }
    }

    // ---- conv2 (no activation) ----
    ull acc2[R][DG];
#pragma unroll
    for (int r = 0; r < R; r++)
#pragma unroll
        for (int j = 0; j < DG; j++) acc2[r][j] = pack2(s.bp2[j], 0.0f);
#pragma unroll
    for (int k = 0; k < DG; k++) {
        const ulonglong2* wrow = (const ulonglong2*)(s.p2 + k * DG);
        ulonglong2 w0 = wrow[0], w1 = wrow[1], w2 = wrow[2], w3 = wrow[3];
#pragma unroll
        for (int r = 0; r < R; r++) {
            ull vv = splat2(h[r][k]);
            acc2[r][0] = ffma2(vv, w0.x, acc2[r][0]);
            acc2[r][1] = ffma2(vv, w0.y, acc2[r][1]);
            acc2[r][2] = ffma2(vv, w1.x, acc2[r][2]);
            acc2[r][3] = ffma2(vv, w1.y, acc2[r][3]);
            acc2[r][4] = ffma2(vv, w2.x, acc2[r][4]);
            acc2[r][5] = ffma2(vv, w2.y, acc2[r][5]);
            acc2[r][6] = ffma2(vv, w3.x, acc2[r][6]);
            acc2[r][7] = ffma2(vv, w3.y, acc2[r][7]);
        }
    }
    float m2[R][DG], s2[R][DG];
#pragma unroll
    for (int r = 0; r < R; r++)
#pragma unroll
        for (int j = 0; j < DG; j++) {
            float lo, hi; unpack2(acc2[r][j], lo, hi);
            m2[r][j] = fmaxf(lo, 0.0f); s2[r][j] = hi;
        }

    float agg2[R][DG];
#pragma unroll
    for (int r = 0; r < R; r++) star_agg(m2[r], agg2[r], lane);

    const bool b4 = (lane & 16) != 0;
    const bool b3 = (lane & 8) != 0;
    const bool b2 = (lane & 4) != 0;

#pragma unroll
    for (int r = 0; r < R; r++) {
        ull gacc[4];
#pragma unroll
        for (int q = 0; q < 4; q++)
            gacc[q] = pack2(s2[r][2 * q] + s.bc2[2 * q], s2[r][2 * q + 1] + s.bc2[2 * q + 1]);
#pragma unroll
        for (int k = 0; k < DG; k++) {
            const ulonglong2* wn = (const ulonglong2*)(s.wn2) + k * 2;
            ulonglong2 wa = wn[0], wb = wn[1];
            ull vv = splat2(agg2[r][k]);
            gacc[0] = ffma2(vv, wa.x, gacc[0]);
            gacc[1] = ffma2(vv, wa.y, gacc[1]);
            gacc[2] = ffma2(vv, wb.x, gacc[2]);
            gacc[3] = ffma2(vv, wb.y, gacc[3]);
        }

        // ---- avg pool: feature-split butterfly sum ----
        float g[DG];
#pragma unroll
        for (int q = 0; q < 4; q++) unpack2(gacc[q], g[2 * q], g[2 * q + 1]);
        float fA[4];
#pragma unroll
        for (int k = 0; k < 4; k++) {
            float snd = b4 ? g[k] : g[4 + k];
            float kp  = b4 ? g[4 + k] : g[k];
            fA[k] = kp + __shfl_xor_sync(FULL_MASK, snd, 16);
        }
        float fB[2];
#pragma unroll
        for (int k = 0; k < 2; k++) {
            float snd = b3 ? fA[k] : fA[2 + k];
            float kp  = b3 ? fA[2 + k] : fA[k];
            fB[k] = kp + __shfl_xor_sync(FULL_MASK, snd, 8);
        }
        float v = (b2 ? fB[1] : fB[0]) +
                  __shfl_xor_sync(FULL_MASK, b2 ? fB[0] : fB[1], 4);
        v += __shfl_xor_sync(FULL_MASK, v, 2);
        v += __shfl_xor_sync(FULL_MASK, v, 1);
        // lane 4j holds sum of feature j
        if (((lane & 3) == 0) && (b0 + r < B))
            g_pooled[(size_t)(b0 + r) * DG + (lane >> 2)] = v * (1.0f / (float)NN);
    }
}

// ---------------------------------------------------------------------------
// MLP kernel (R6 v3, measured 64.4us): one thread handles TWO batch elements
// so each weight LDS.128 feeds 4 FFMA2. Activations in small local arrays.
// ---------------------------------------------------------------------------

#define M_W1 0
#define M_B1 1536
#define M_W2 1600
#define M_B2 5696
#define M_W3 5760
#define M_B3 9856
#define M_W4 9920
#define M_B4 10176
#define M_TOT 10180

template<int NIN>
__device__ __forceinline__ void layer2(const ulonglong2* __restrict__ w,
                                       const float* __restrict__ bias,
                                       const float* __restrict__ inA,
                                       const float* __restrict__ inB,
                                       float* __restrict__ outA,
                                       float* __restrict__ outB)
{
#pragma unroll
    for (int c = 0; c < 2; c++) {
        ull accA[16], accB[16];
#pragma unroll
        for (int q = 0; q < 16; q++) {
            ull bv = pack2(bias[32 * c + 2 * q], bias[32 * c + 2 * q + 1]);
            accA[q] = bv; accB[q] = bv;
        }
#pragma unroll 2
        for (int i = 0; i < NIN; i++) {
            ull va = splat2(inA[i]);
            ull vb = splat2(inB[i]);
            const ulonglong2* wr = w + i * 16 + 8 * c;
#pragma unroll
            for (int q2 = 0; q2 < 8; q2++) {
                ulonglong2 ww = wr[q2];
                accA[2 * q2]     = ffma2(va, ww.x, accA[2 * q2]);
                accA[2 * q2 + 1] = ffma2(va, ww.y, accA[2 * q2 + 1]);
                accB[2 * q2]     = ffma2(vb, ww.x, accB[2 * q2]);
                accB[2 * q2 + 1] = ffma2(vb, ww.y, accB[2 * q2 + 1]);
            }
        }
#pragma unroll
        for (int q = 0; q < 16; q++) {
            float lo, hi;
            unpack2(accA[q], lo, hi);
            outA[32 * c + 2 * q]     = fmaxf(lo, 0.0f);
            outA[32 * c + 2 * q + 1] = fmaxf(hi, 0.0f);
            unpack2(accB[q], lo, hi);
            outB[32 * c + 2 * q]     = fmaxf(lo, 0.0f);
            outB[32 * c + 2 * q + 1] = fmaxf(hi, 0.0f);
        }
    }
}

__global__ __launch_bounds__(128, 4) void mlp_kernel(
    const float* __restrict__ other,
    const float* __restrict__ W1, const float* __restrict__ b1,
    const float* __restrict__ W2, const float* __restrict__ b2,
    const float* __restrict__ W3, const float* __restrict__ b3,
    const float* __restrict__ W4, const float* __restrict__ b4,
    float* __restrict__ out, int B)
{
    __shared__ __align__(16) float sm[M_TOT];
    int tid = threadIdx.x;
    for (int i = tid; i < 1536; i += 128) sm[M_W1 + i] = W1[i];
    for (int i = tid; i < 4096; i += 128) { sm[M_W2 + i] = W2[i]; sm[M_W3 + i] = W3[i]; }
    for (int i = tid; i < 256;  i += 128) sm[M_W4 + i] = W4[i];
    if (tid < 64) { sm[M_B1 + tid] = b1[tid]; sm[M_B2 + tid] = b2[tid]; sm[M_B3 + tid] = b3[tid]; }
    if (tid < 4)  sm[M_B4 + tid] = b4[tid];
    __syncthreads();

    int e0 = blockIdx.x * 256 + tid;   // this thread: elems e0, e0+128
    int e1 = e0 + 128;
    if (e0 >= B) return;
    int e1c = (e1 < B) ? e1 : e0;      // clamp (garbage ok, store guarded)

    float inA[DG + DC], inB[DG + DC];
    {
        const float4* pp = (const float4*)(g_pooled + (size_t)e0 * DG);
        float4 p0 = pp[0], p1 = pp[1];
        inA[0] = p0.x; inA[1] = p0.y; inA[2] = p0.z; inA[3] = p0.w;
        inA[4] = p1.x; inA[5] = p1.y; inA[6] = p1.z; inA[7] = p1.w;
        const float4* op = (const float4*)(other + (size_t)e0 * DC);
#pragma unroll
        for (int k = 0; k < 4; k++) {
            float4 v = op[k];
            inA[8 + 4 * k + 0] = v.x; inA[8 + 4 * k + 1] = v.y;
            inA[8 + 4 * k + 2] = v.z; inA[8 + 4 * k + 3] = v.w;
        }
        const float4* pp2 = (const float4*)(g_pooled + (size_t)e1c * DG);
        float4 q0 = pp2[0], q1 = pp2[1];
        inB[0] = q0.x; inB[1] = q0.y; inB[2] = q0.z; inB[3] = q0.w;
        inB[4] = q1.x; inB[5] = q1.y; inB[6] = q1.z; inB[7] = q1.w;
        const float4* op2 = (const float4*)(other + (size_t)e1c * DC);
#pragma unroll
        for (int k = 0; k < 4; k++) {
            float4 v = op2[k];
            inB[8 + 4 * k + 0] = v.x; inB[8 + 4 * k + 1] = v.y;
            inB[8 + 4 * k + 2] = v.z; inB[8 + 4 * k + 3] = v.w;
        }
    }

    const ulonglong2* w1 = (const ulonglong2*)(sm + M_W1);
    const ulonglong2* w2 = (const ulonglong2*)(sm + M_W2);
    const ulonglong2* w3 = (const ulonglong2*)(sm + M_W3);

    float hA[HID], hB[HID], gA[HID], gB[HID];
    layer2<DG + DC>(w1, sm + M_B1, inA, inB, hA, hB);
    layer2<HID>(w2, sm + M_B2, hA, hB, gA, gB);
    layer2<HID>(w3, sm + M_B3, gA, gB, hA, hB);

    // output layer: 64 -> 4, tanh, both elems
    const ulonglong2* w4 = (const ulonglong2*)(sm + M_W4);
    ull a01A = pack2(sm[M_B4 + 0], sm[M_B4 + 1]);
    ull a23A = pack2(sm[M_B4 + 2], sm[M_B4 + 3]);
    ull a01B = a01A, a23B = a23A;
#pragma unroll 2
    for (int i = 0; i < HID; i++) {
        ulonglong2 ww = w4[i];
        ull va = splat2(hA[i]);
        ull vb = splat2(hB[i]);
        a01A = ffma2(va, ww.x, a01A);
        a23A = ffma2(va, ww.y, a23A);
        a01B = ffma2(vb, ww.x, a01B);
        a23B = ffma2(vb, ww.y, a23B);
    }
    float o0, o1, o2, o3;
    unpack2(ftanh2(a01A), o0, o1);
    unpack2(ftanh2(a23A), o2, o3);
    ((float4*)out)[e0] = make_float4(o0, o1, o2, o3);
    if (e1 < B) {
        unpack2(ftanh2(a01B), o0, o1);
        unpack2(ftanh2(a23B), o2, o3);
        ((float4*)out)[e1] = make_float4(o0, o1, o2, o3);
    }
}

// ---------------------------------------------------------------------------

extern "C" void kernel_launch(void* const* d_in, const int* in_sizes, int n_in,
                              void* d_out, int out_size)
{
    const float* x     = (const float*)d_in[0];
    const float* other = (const float*)d_in[1];
    // d_in[2..4] = src/dst/node_seg: star graph is fixed, structure hardcoded.
    const float* Wp1 = (const float*)d_in[5];
    const float* bp1 = (const float*)d_in[6];
    const float* Ws1 = (const float*)d_in[7];
    const float* Wn1 = (const float*)d_in[8];
    const float* bc1 = (const float*)d_in[9];
    const float* Wp2 = (const float*)d_in[10];
    const float* bp2 = (const float*)d_in[11];
    const float* Ws2 = (const float*)d_in[12];
    const float* Wn2 = (const float*)d_in[13];
    const float* bc2 = (const float*)d_in[14];
    const float* W1  = (const float*)d_in[15];
    const float* bf1 = (const float*)d_in[16];
    const float* W2  = (const float*)d_in[17];
    const float* bf2 = (const float*)d_in[18];
    const float* W3  = (const float*)d_in[19];
    const float* bf3 = (const float*)d_in[20];
    const float* W4  = (const float*)d_in[21];
    const float* bf4 = (const float*)d_in[22];

    int B = in_sizes[1] / DC;   // other_obs is [B, 16]

    conv_kernel<<<(B + 4 * R - 1) / (4 * R), 128>>>(x, Wp1, bp1, Ws1, Wn1, bc1,
                                                    Wp2, bp2, Ws2, Wn2, bc2, B);
    mlp_kernel<<<(B + 255) / 256, 128>>>(other, W1, bf1, W2, bf2, W3, bf3,
                                         W4, bf4, (float*)d_out, B);
}